// round 6
// baseline (speedup 1.0000x reference)
#include <cuda_runtime.h>
#include <cstdint>
#include <math_constants.h>

// KineticOptimalDiscreteEulerSolver — closed-form collapse.
//
// Inputs (metadata order):
//   d_in[0]: logits   float32 [4*16*1024] = 65536
//   d_in[1]: source_p float32 [1024]
//   d_in[2]: x_t      int32   [64]
//   d_in[3]: t        float32 [1]
// Output: float32 [4,16,1024]
//
// Algebra: with p_t = (1-k)*sp + k*onehot(x1), pdot = onehot(x1) - sp, the
// antisymmetric flux simplifies exactly to A(i,j) = sp[i]*[j==x1] - [i==x1]*sp[j]
// (all k terms cancel). Clamped row at i = x_t:
//   x_t == x1 : all zeros
//   x_t != x1 : out[x1] = sp[x_t] / ((1-k)*sp[x1] + k + EPS),  out[x_t] = -out[x1]
// x1 = argmax(logits + gumbel) = jax.random.categorical(key(1), logits) with the
// PARTITIONABLE threefry scheme (jax_threefry_partitionable=True, modern default):
//   counter (hi, lo) = (0, flat_index e);  bits = out0 ^ out1 of threefry2x32.

#define V        1024
#define NTOK     64
#define EPSV     1e-8f
#define TINYF    1.17549435e-38f

__device__ __forceinline__ uint32_t rotl32(uint32_t x, uint32_t r) {
    return (x << r) | (x >> (32u - r));
}

// JAX threefry2x32, key = (0, 1) [jax.random.key(1)], returns out0 ^ out1
// (the partitionable 32-bit random-bits reduction).
__device__ __forceinline__ uint32_t threefry_xor_0_1(uint32_t x0, uint32_t x1) {
    const uint32_t ks0 = 0u, ks1 = 1u;
    const uint32_t ks2 = 0x1BD11BDAu ^ ks0 ^ ks1;   // 0x1BD11BDB
    x0 += ks0; x1 += ks1;
#define TF_RND(r) { x0 += x1; x1 = rotl32(x1, r); x1 ^= x0; }
    TF_RND(13) TF_RND(15) TF_RND(26) TF_RND(6)
    x0 += ks1; x1 += ks2 + 1u;
    TF_RND(17) TF_RND(29) TF_RND(16) TF_RND(24)
    x0 += ks2; x1 += ks0 + 2u;
    TF_RND(13) TF_RND(15) TF_RND(26) TF_RND(6)
    x0 += ks0; x1 += ks1 + 3u;
    TF_RND(17) TF_RND(29) TF_RND(16) TF_RND(24)
    x0 += ks1; x1 += ks2 + 4u;
    TF_RND(13) TF_RND(15) TF_RND(26) TF_RND(6)
    x0 += ks2; x1 += ks0 + 5u;
#undef TF_RND
    return x0 ^ x1;
}

// JAX gumbel(key(1), (4,16,1024), f32), partitionable path, flat element e:
// 64-bit counter e -> (hi=0, lo=e); bits = tf_out0 ^ tf_out1;
// uniform u = max(tiny, (bitcast((bits>>9)|0x3f800000)-1) * (1-tiny) + tiny);
// gumbel = -log(-log(u)).  Logs in double for correct rounding (immune to
// --use_fast_math logf degradation); result cast to f32.
__device__ __forceinline__ float jax_gumbel(uint32_t e) {
    uint32_t bits = threefry_xor_0_1(0u, e);
    float f = __uint_as_float((bits >> 9) | 0x3F800000u) - 1.0f;
    float u = fmaxf(TINYF, f * (1.0f - TINYF) + TINYF);
    return (float)(-log(-log((double)u)));
}

__global__ void __launch_bounds__(256, 1)
kinetic_euler_kernel(const float* __restrict__ logits,
                     const float* __restrict__ source_p,
                     const int*   __restrict__ x_t,
                     const float* __restrict__ t,
                     float*       __restrict__ out) {
    const int n    = blockIdx.x;     // token 0..63
    const int tid  = threadIdx.x;    // 0..255
    const int wid  = tid >> 5;
    const int lane = tid & 31;

    __shared__ float wVal[8];
    __shared__ int   wIdx[8];
    __shared__ float wSum[8];

    const float* lrow = logits + n * V;
    float*       orow = out    + n * V;

    // vectorized zero-fill: 256 threads x float4 = 1024 floats
    reinterpret_cast<float4*>(orow)[tid] = make_float4(0.f, 0.f, 0.f, 0.f);

    // per-thread: sum of source_p, argmax of logits+gumbel
    float psum = 0.0f;
    float best = -CUDART_INF_F;
    int   bidx = 0;
#pragma unroll
    for (int w = 0; w < 4; w++) {
        int v = tid + 256 * w;                 // ascending: within-thread strict > keeps lowest idx
        psum += source_p[v];
        uint32_t e = (uint32_t)(n * V + v);
        float val = lrow[v] + jax_gumbel(e);
        if (val > best) { best = val; bidx = v; }
    }

    // warp-level reduce (sum + argmax, ties -> lower index like jnp.argmax)
#pragma unroll
    for (int off = 16; off > 0; off >>= 1) {
        psum += __shfl_xor_sync(0xFFFFFFFFu, psum, off);
        float v2 = __shfl_xor_sync(0xFFFFFFFFu, best, off);
        int   i2 = __shfl_xor_sync(0xFFFFFFFFu, bidx, off);
        if (v2 > best || (v2 == best && i2 < bidx)) { best = v2; bidx = i2; }
    }
    if (lane == 0) { wVal[wid] = best; wIdx[wid] = bidx; wSum[wid] = psum; }
    __syncthreads();

    if (tid == 0) {
        float S = wSum[0];
        best = wVal[0]; bidx = wIdx[0];
#pragma unroll
        for (int w = 1; w < 8; w++) {
            S += wSum[w];
            float v2 = wVal[w]; int i2 = wIdx[w];
            if (v2 > best || (v2 == best && i2 < bidx)) { best = v2; bidx = i2; }
        }
        int x1  = bidx;
        int xti = __ldg(x_t + n);
        if (x1 != xti) {
            float k  = __ldg(t);
            float si = __ldg(source_p + xti) / S;         // normalized sp[x_t]
            float sj = __ldg(source_p + x1)  / S;         // normalized sp[x1]
            float denom = (1.0f - k) * sj + k + EPSV;     // p_t[x1] + EPS
            float val = si / denom;
            orow[x1]  = val;    // off-diagonal jump rate
            orow[xti] = -val;   // diagonal correction (row sums to zero)
        }
        // x_t == x1: row stays all-zero (flux is non-positive everywhere)
    }
}

extern "C" void kernel_launch(void* const* d_in, const int* in_sizes, int n_in,
                              void* d_out, int out_size) {
    const float* logits   = (const float*)d_in[0];
    const float* source_p = (const float*)d_in[1];
    const int*   x_t      = (const int*)  d_in[2];
    const float* t        = (const float*)d_in[3];
    float*       out      = (float*)d_out;
    kinetic_euler_kernel<<<NTOK, 256>>>(logits, source_p, x_t, t, out);
}

// round 8
// speedup vs baseline: 2.8413x; 2.8413x over previous
#include <cuda_runtime.h>
#include <cstdint>
#include <math_constants.h>

// KineticOptimalDiscreteEulerSolver — closed-form collapse, full-chip version.
//
// Inputs: d_in[0] logits f32[64*1024], d_in[1] source_p f32[1024],
//         d_in[2] x_t i32[64], d_in[3] t f32[1].  Output f32[64*1024].
//
// Algebra: clamped antisymmetric-flux row at i = x_t has <= 2 nonzeros:
//   x_t == x1 : all zeros
//   x_t != x1 : out[x1] = sp[x_t] / ((1-k)*sp[x1] + k + EPS), out[x_t] = -out[x1]
// x1 = argmax(logits + gumbel) = jax.random.categorical(key(1), logits) with the
// PARTITIONABLE threefry scheme (verified passing in R6): counter (0, e),
// bits = out0 ^ out1 of threefry2x32(key=(0,1)).
//
// Parallelism: 4 blocks per token (grid=256 covers all 148 SMs), 1 element per
// thread. Cross-block argmax via u64 atomicMax on (ordered_val<<32 | 1023-idx)
// — order-independent => deterministic; ties -> lower index (jnp.argmax).
// Last block per token (ticket counter) writes the finals and resets scratch
// so every graph replay starts from the same state.

#define V        1024
#define NTOK     64
#define QPT      4          // blocks per token
#define QELEM    256        // elements per block
#define EPSV     1e-8f
#define TINYF    1.17549435e-38f

__device__ unsigned long long g_amax[NTOK];  // zero-init; reset by last block each launch
__device__ unsigned int       g_cnt[NTOK];

__device__ __forceinline__ uint32_t rotl32(uint32_t x, uint32_t r) {
    return (x << r) | (x >> (32u - r));
}

// JAX threefry2x32, key = (0,1), returns out0 ^ out1 (partitionable reduction).
__device__ __forceinline__ uint32_t threefry_xor_0_1(uint32_t x0, uint32_t x1) {
    const uint32_t ks0 = 0u, ks1 = 1u;
    const uint32_t ks2 = 0x1BD11BDAu ^ ks0 ^ ks1;   // 0x1BD11BDB
    x0 += ks0; x1 += ks1;
#define TF_RND(r) { x0 += x1; x1 = rotl32(x1, r); x1 ^= x0; }
    TF_RND(13) TF_RND(15) TF_RND(26) TF_RND(6)
    x0 += ks1; x1 += ks2 + 1u;
    TF_RND(17) TF_RND(29) TF_RND(16) TF_RND(24)
    x0 += ks2; x1 += ks0 + 2u;
    TF_RND(13) TF_RND(15) TF_RND(26) TF_RND(6)
    x0 += ks0; x1 += ks1 + 3u;
    TF_RND(17) TF_RND(29) TF_RND(16) TF_RND(24)
    x0 += ks1; x1 += ks2 + 4u;
    TF_RND(13) TF_RND(15) TF_RND(26) TF_RND(6)
    x0 += ks2; x1 += ks0 + 5u;
#undef TF_RND
    return x0 ^ x1;
}

// JAX gumbel(key(1), ...) for flat element e, partitionable path, f32 logs
// (XLA evaluates these logs in f32 too; ulp-level noise only).
__device__ __forceinline__ float jax_gumbel(uint32_t e) {
    uint32_t bits = threefry_xor_0_1(0u, e);
    float f = __uint_as_float((bits >> 9) | 0x3F800000u) - 1.0f;
    float u = fmaxf(TINYF, f * (1.0f - TINYF) + TINYF);
    return -logf(-logf(u));
}

__global__ void __launch_bounds__(256, 2)
kinetic_euler_kernel(const float* __restrict__ logits,
                     const float* __restrict__ source_p,
                     const int*   __restrict__ x_t,
                     const float* __restrict__ t,
                     float*       __restrict__ out) {
    const int bid  = blockIdx.x;
    const int n    = bid >> 2;       // token
    const int q    = bid & 3;        // quarter of the row
    const int tid  = threadIdx.x;    // 0..255
    const int wid  = tid >> 5;
    const int lane = tid & 31;

    __shared__ float wVal[8];
    __shared__ int   wIdx[8];
    __shared__ float wSum[8];

    const float* lrow = logits + n * V;
    float*       orow = out    + n * V;
    const int    v    = q * QELEM + tid;

    // zero-fill this block's quarter of the output row
    orow[v] = 0.0f;

    // full source_p sum, replicated per block with identical reduction order
    // (bit-deterministic S everywhere, no float atomics needed)
    float psum = source_p[tid] + source_p[tid + 256]
               + source_p[tid + 512] + source_p[tid + 768];

    // one gumbel per thread
    float best = lrow[v] + jax_gumbel((uint32_t)(n * V + v));
    int   bidx = v;

    // warp reduce: sum + argmax (ties -> lower index)
#pragma unroll
    for (int off = 16; off > 0; off >>= 1) {
        psum += __shfl_xor_sync(0xFFFFFFFFu, psum, off);
        float v2 = __shfl_xor_sync(0xFFFFFFFFu, best, off);
        int   i2 = __shfl_xor_sync(0xFFFFFFFFu, bidx, off);
        if (v2 > best || (v2 == best && i2 < bidx)) { best = v2; bidx = i2; }
    }
    if (lane == 0) { wVal[wid] = best; wIdx[wid] = bidx; wSum[wid] = psum; }
    __syncthreads();

    if (tid == 0) {
        float S = wSum[0];
        best = wVal[0]; bidx = wIdx[0];
#pragma unroll
        for (int w = 1; w < 8; w++) {
            S += wSum[w];
            float v2 = wVal[w]; int i2 = wIdx[w];
            if (v2 > best || (v2 == best && i2 < bidx)) { best = v2; bidx = i2; }
        }

        // order-preserving float->uint map (monotone increasing)
        uint32_t ov = __float_as_uint(best);
        ov = (ov & 0x80000000u) ? ~ov : (ov | 0x80000000u);
        // pack: higher val wins; on equal val, higher (V-1-idx) = lower idx wins
        unsigned long long key =
            ((unsigned long long)ov << 32) | (unsigned int)(V - 1 - bidx);

        atomicMax(&g_amax[n], key);
        __threadfence();                      // publish zero-fill + max before arrival
        unsigned int old = atomicAdd(&g_cnt[n], 1u);
        if (old == QPT - 1) {                 // last block for this token
            __threadfence();                  // order vs other blocks' publishes
            unsigned long long kk = atomicAdd(&g_amax[n], 0ULL);
            int x1  = V - 1 - (int)(kk & 0xFFFFFFFFu);
            int xti = __ldg(x_t + n);
            if (x1 != xti) {
                float k  = __ldg(t);
                float si = __ldg(source_p + xti) / S;        // normalized sp[x_t]
                float sj = __ldg(source_p + x1)  / S;        // normalized sp[x1]
                float denom = (1.0f - k) * sj + k + EPSV;    // p_t[x1] + EPS
                float w = si / denom;
                orow[x1]  = w;     // off-diagonal jump rate
                orow[xti] = -w;    // diagonal correction (row sums to zero)
            }
            // reset scratch for the next (graph-replayed) launch — no other
            // writers remain for this token, so plain stores are safe
            g_amax[n] = 0ULL;
            g_cnt[n]  = 0u;
        }
    }
}

extern "C" void kernel_launch(void* const* d_in, const int* in_sizes, int n_in,
                              void* d_out, int out_size) {
    const float* logits   = (const float*)d_in[0];
    const float* source_p = (const float*)d_in[1];
    const int*   x_t      = (const int*)  d_in[2];
    const float* t        = (const float*)d_in[3];
    float*       out      = (float*)d_out;
    kinetic_euler_kernel<<<NTOK * QPT, QELEM>>>(logits, source_p, x_t, t, out);
}